// round 11
// baseline (speedup 1.0000x reference)
#include <cuda_runtime.h>

// Problem shape (fixed by the dataset)
#define BB 4
#define SS 256
#define EE 256
#define MM (BB * SS)

// Scratch: pi[m,f] and (pj[m,f] + b[f]) — 1 MB each
__device__ float g_pi [MM * EE];
__device__ float g_pjb[MM * EE];

// ---------------------------------------------------------------------------
// Kernel 1: dual GEMM, single-load / sync-free mainloop, duplicated-x SMEM.
// 128 blocks x 128 threads, BM=32, BN=64, full K=256 resident in SMEM (~201KB
// dynamic). Thread tile 4m x 4f x 2mat, packed fma.rn.f32x2.
// x is stored as {v,v} float2 so one LDS.64 yields the packed broadcast
// operand directly (no mov.b64 pair-building in the inner loop).
// ---------------------------------------------------------------------------
#define BM 32
#define BN 64

#define X2STR 258     // s_x2 row stride in float2 units: 2064B = 129*16 (16B-aligned)
#define WSTR  68      // s_w row stride (floats): 272B = 17*16

#define SX_FLOATS (BM * X2STR * 2)            // 16512 floats (66 KB)
#define SW_FLOATS (EE * WSTR)                 // 17408 floats (69.6 KB)
#define SMEM_FLOATS (SX_FLOATS + 2 * SW_FLOATS)
#define SMEM_BYTES (SMEM_FLOATS * 4)          // 205,312 B < 227 KB carveout

__device__ __forceinline__ void fma2(unsigned long long& acc,
                                     unsigned long long a,
                                     unsigned long long b)
{
    asm("fma.rn.f32x2 %0, %1, %2, %0;" : "+l"(acc) : "l"(a), "l"(b));
}

__global__ __launch_bounds__(128)
void gemm_kernel(const float* __restrict__ x,
                 const float* __restrict__ W,
                 const float* __restrict__ bias)
{
    extern __shared__ float sm[];
    float* s_x2 = sm;                         // [BM][X2STR float2] duplicated x
    float* s_w1 = sm + SX_FLOATS;             // [EE][WSTR] (k-major, transposed)
    float* s_w2 = sm + SX_FLOATS + SW_FLOATS;

    const int m0  = blockIdx.x * BM;
    const int f0  = blockIdx.y * BN;
    const int tid = threadIdx.x;

    const int ty  = tid >> 4;    // 0..7  -> m (4 rows each)
    const int tx  = tid & 15;    // 0..15 -> f (4 cols = 2 f32x2 pairs)

    // ---------------- load x: duplicate each scalar into a float2 -----------
    // 2048 float4 source reads; each expands to 2 STS.128 of {x,x,y,y}/{z,z,w,w}
    #pragma unroll
    for (int i = 0; i < 16; ++i) {
        int idx = tid + i * 128;              // 0..2047
        int row = idx >> 6;                   // m 0..31
        int c4  = idx & 63;                   // k-float4 0..63
        float4 v = *(const float4*)&x[(size_t)(m0 + row) * EE + c4 * 4];
        float* d = s_x2 + (row * X2STR + c4 * 4) * 2;
        *(float4*)(d + 0) = make_float4(v.x, v.x, v.y, v.y);
        *(float4*)(d + 4) = make_float4(v.z, v.z, v.w, v.w);
    }

    // ---------------- load W: 4x4 register transpose -> [k][f] --------------
    #pragma unroll
    for (int i = 0; i < 8; ++i) {
        int t4 = tid + i * 128;               // 0..1023
        int fg = t4 >> 6;                     // f-group 0..15
        int kg = t4 & 63;                     // k-group 0..63
        const float* wb = W + (size_t)(f0 + fg * 4) * (2 * EE) + kg * 4;

        float4 a0 = *(const float4*)(wb + 0 * (2 * EE));
        float4 a1 = *(const float4*)(wb + 1 * (2 * EE));
        float4 a2 = *(const float4*)(wb + 2 * (2 * EE));
        float4 a3 = *(const float4*)(wb + 3 * (2 * EE));
        float* d1 = s_w1 + (kg * 4) * WSTR + fg * 4;
        *(float4*)(d1 + 0 * WSTR) = make_float4(a0.x, a1.x, a2.x, a3.x);
        *(float4*)(d1 + 1 * WSTR) = make_float4(a0.y, a1.y, a2.y, a3.y);
        *(float4*)(d1 + 2 * WSTR) = make_float4(a0.z, a1.z, a2.z, a3.z);
        *(float4*)(d1 + 3 * WSTR) = make_float4(a0.w, a1.w, a2.w, a3.w);

        float4 b0 = *(const float4*)(wb + EE + 0 * (2 * EE));
        float4 b1 = *(const float4*)(wb + EE + 1 * (2 * EE));
        float4 b2 = *(const float4*)(wb + EE + 2 * (2 * EE));
        float4 b3 = *(const float4*)(wb + EE + 3 * (2 * EE));
        float* d2 = s_w2 + (kg * 4) * WSTR + fg * 4;
        *(float4*)(d2 + 0 * WSTR) = make_float4(b0.x, b1.x, b2.x, b3.x);
        *(float4*)(d2 + 1 * WSTR) = make_float4(b0.y, b1.y, b2.y, b3.y);
        *(float4*)(d2 + 2 * WSTR) = make_float4(b0.z, b1.z, b2.z, b3.z);
        *(float4*)(d2 + 3 * WSTR) = make_float4(b0.w, b1.w, b2.w, b3.w);
    }

    __syncthreads();   // the only barrier

    // ---------------- sync-free mainloop over full K ------------------------
    unsigned long long acc1[4][2] = {};
    unsigned long long acc2[4][2] = {};

    const unsigned long long* ax0 =
        (const unsigned long long*)(s_x2 + (ty * 4 + 0) * X2STR * 2);
    const unsigned long long* ax1 =
        (const unsigned long long*)(s_x2 + (ty * 4 + 1) * X2STR * 2);
    const unsigned long long* ax2 =
        (const unsigned long long*)(s_x2 + (ty * 4 + 2) * X2STR * 2);
    const unsigned long long* ax3 =
        (const unsigned long long*)(s_x2 + (ty * 4 + 3) * X2STR * 2);

    #pragma unroll 1
    for (int ko = 0; ko < EE; ko += 16) {
        #pragma unroll
        for (int k2 = 0; k2 < 16; ++k2) {
            const int k = ko + k2;
            unsigned long long a0 = ax0[k];   // LDS.64, packed {v,v}
            unsigned long long a1 = ax1[k];
            unsigned long long a2 = ax2[k];
            unsigned long long a3 = ax3[k];
            const ulonglong2 w1 = *(const ulonglong2*)&s_w1[k * WSTR + tx * 4];
            const ulonglong2 w2 = *(const ulonglong2*)&s_w2[k * WSTR + tx * 4];

            fma2(acc1[0][0], a0, w1.x); fma2(acc1[0][1], a0, w1.y);
            fma2(acc1[1][0], a1, w1.x); fma2(acc1[1][1], a1, w1.y);
            fma2(acc1[2][0], a2, w1.x); fma2(acc1[2][1], a2, w1.y);
            fma2(acc1[3][0], a3, w1.x); fma2(acc1[3][1], a3, w1.y);

            fma2(acc2[0][0], a0, w2.x); fma2(acc2[0][1], a0, w2.y);
            fma2(acc2[1][0], a1, w2.x); fma2(acc2[1][1], a1, w2.y);
            fma2(acc2[2][0], a2, w2.x); fma2(acc2[2][1], a2, w2.y);
            fma2(acc2[3][0], a3, w2.x); fma2(acc2[3][1], a3, w2.y);
        }
    }

    // ---------------- epilogue ---------------------------------------------
    float4 bi = *(const float4*)&bias[f0 + tx * 4];

    #pragma unroll
    for (int i = 0; i < 4; ++i) {
        int m = m0 + ty * 4 + i;
        float2 p0 = *(float2*)&acc1[i][0];
        float2 p1 = *(float2*)&acc1[i][1];
        float2 q0 = *(float2*)&acc2[i][0];
        float2 q1 = *(float2*)&acc2[i][1];
        *(float4*)&g_pi [(size_t)m * EE + f0 + tx * 4] =
            make_float4(p0.x, p0.y, p1.x, p1.y);
        *(float4*)&g_pjb[(size_t)m * EE + f0 + tx * 4] =
            make_float4(q0.x + bi.x, q0.y + bi.y, q1.x + bi.z, q1.y + bi.w);
    }
}

// ---------------------------------------------------------------------------
// Kernel 2: broadcast add (frozen: 2048 blocks, ~43us — DRAM-write ceiling).
// ---------------------------------------------------------------------------
#define TI 4
#define TJ 32
#define E4 (EE / 4)

__global__ __launch_bounds__(256)
void add_kernel(float* __restrict__ out)
{
    __shared__ float4 s_pj[TJ * E4];   // 32 KB

    const int b   = blockIdx.z;
    const int i0  = blockIdx.y * TI;
    const int j0  = blockIdx.x * TJ;
    const int tid = threadIdx.x;
    const int e4  = tid & 63;
    const int jq  = tid >> 6;

    const float4* pi4 = (const float4*)g_pi  + (size_t)(b * SS + i0) * E4;
    const float4* pj4 = (const float4*)g_pjb + (size_t)(b * SS + j0) * E4;

    #pragma unroll
    for (int r = 0; r < 8; ++r)
        s_pj[tid + r * 256] = pj4[tid + r * 256];

    float4 pi_r[TI];
    #pragma unroll
    for (int i = 0; i < TI; ++i)
        pi_r[i] = pi4[i * E4 + e4];

    __syncthreads();

    float4* out4 = (float4*)out + ((size_t)(b * SS + i0) * SS + j0) * E4;

    #pragma unroll
    for (int jj = 0; jj < TJ / 4; ++jj) {
        int j = jq + jj * 4;
        float4 c = s_pj[j * E4 + e4];
        #pragma unroll
        for (int i = 0; i < TI; ++i) {
            float4 v = make_float4(pi_r[i].x + c.x, pi_r[i].y + c.y,
                                   pi_r[i].z + c.z, pi_r[i].w + c.w);
            __stcs(&out4[((size_t)i * SS + j) * E4 + e4], v);
        }
    }
}

// ---------------------------------------------------------------------------
extern "C" void kernel_launch(void* const* d_in, const int* in_sizes, int n_in,
                              void* d_out, int out_size)
{
    const float* x    = (const float*)d_in[0];   // component_repr [4,256,256]
    const float* W    = (const float*)d_in[1];   // W [256,512]
    const float* bias = (const float*)d_in[2];   // b [256]
    float* out = (float*)d_out;                  // [4,256,256,256]

    // raise dynamic smem cap (idempotent attribute set, not an allocation)
    cudaFuncSetAttribute(gemm_kernel,
                         cudaFuncAttributeMaxDynamicSharedMemorySize,
                         SMEM_BYTES);

    dim3 gGemm(MM / BM, EE / BN);                // 32 x 4 = 128 blocks
    gemm_kernel<<<gGemm, 128, SMEM_BYTES>>>(x, W, bias);

    dim3 gAdd(SS / TJ, SS / TI, BB);             // 8 x 64 x 4 = 2048 blocks
    add_kernel<<<gAdd, 256>>>(out);
}

// round 12
// speedup vs baseline: 1.0022x; 1.0022x over previous
#include <cuda_runtime.h>

// Problem shape (fixed by the dataset)
#define BB 4
#define SS 256
#define EE 256
#define MM (BB * SS)

// Scratch: pi[m,f] and (pj[m,f] + b[f]) — 1 MB each
__device__ float g_pi [MM * EE];
__device__ float g_pjb[MM * EE];

// ---------------------------------------------------------------------------
// Kernel 1: dual GEMM, single-load / sync-free mainloop (R10 structure),
// 128 blocks x 256 threads. BM=32, BN=64, full K=256 resident in SMEM
// (~172KB dynamic). Thread tile 2m x 4f x 2mat, packed fma.rn.f32x2.
// 256 threads halve the per-thread load-phase work (the recoverable cost);
// the mainloop keeps the fma pipe saturated (16 FFMA2/SMSP/k).
// ---------------------------------------------------------------------------
#define BM 32
#define BN 64

#define XSTR 260     // s_x row stride (floats): 1040B = 65*16 (16B-aligned)
#define WSTR 68      // s_w row stride (floats): 272B = 17*16

#define SX_FLOATS (BM * XSTR)                 //  8320
#define SW_FLOATS (EE * WSTR)                 // 17408
#define SMEM_FLOATS (SX_FLOATS + 2 * SW_FLOATS)
#define SMEM_BYTES (SMEM_FLOATS * 4)          // 172,544 B

__device__ __forceinline__ void fma2(unsigned long long& acc,
                                     unsigned long long a,
                                     unsigned long long b)
{
    asm("fma.rn.f32x2 %0, %1, %2, %0;" : "+l"(acc) : "l"(a), "l"(b));
}

__device__ __forceinline__ unsigned long long bcast2(float a)
{
    unsigned long long r;
    asm("mov.b64 %0, {%1, %1};" : "=l"(r) : "r"(__float_as_int(a)));
    return r;
}

__global__ __launch_bounds__(256)
void gemm_kernel(const float* __restrict__ x,
                 const float* __restrict__ W,
                 const float* __restrict__ bias)
{
    extern __shared__ float sm[];
    float* s_x  = sm;                         // [BM][XSTR]  (m-major, direct copy)
    float* s_w1 = sm + SX_FLOATS;             // [EE][WSTR]  (k-major, transposed)
    float* s_w2 = sm + SX_FLOATS + SW_FLOATS;

    const int m0  = blockIdx.x * BM;
    const int f0  = blockIdx.y * BN;
    const int tid = threadIdx.x;

    const int ty  = tid >> 4;    // 0..15 -> m (2 rows each)
    const int tx  = tid & 15;    // 0..15 -> f (4 cols = 2 f32x2 pairs)

    // ---------------- load x: direct copy [m][k], coalesced -----------------
    #pragma unroll
    for (int i = 0; i < 8; ++i) {
        int idx = tid + i * 256;              // 0..2047
        int row = idx >> 6;                   // m 0..31
        int c4  = idx & 63;                   // k-float4 0..63
        float4 v = *(const float4*)&x[(size_t)(m0 + row) * EE + c4 * 4];
        *(float4*)&s_x[row * XSTR + c4 * 4] = v;
    }

    // ---------------- load W: 4x4 register transpose -> [k][f] --------------
    // 1024 4x4 tiles per matrix (16 f-groups x 64 k-groups), 4 per thread.
    #pragma unroll
    for (int i = 0; i < 4; ++i) {
        int t4 = tid + i * 256;               // 0..1023
        int fg = t4 >> 6;                     // f-group 0..15
        int kg = t4 & 63;                     // k-group 0..63
        const float* wb = W + (size_t)(f0 + fg * 4) * (2 * EE) + kg * 4;

        float4 a0 = *(const float4*)(wb + 0 * (2 * EE));
        float4 a1 = *(const float4*)(wb + 1 * (2 * EE));
        float4 a2 = *(const float4*)(wb + 2 * (2 * EE));
        float4 a3 = *(const float4*)(wb + 3 * (2 * EE));
        float* d1 = s_w1 + (kg * 4) * WSTR + fg * 4;
        *(float4*)(d1 + 0 * WSTR) = make_float4(a0.x, a1.x, a2.x, a3.x);
        *(float4*)(d1 + 1 * WSTR) = make_float4(a0.y, a1.y, a2.y, a3.y);
        *(float4*)(d1 + 2 * WSTR) = make_float4(a0.z, a1.z, a2.z, a3.z);
        *(float4*)(d1 + 3 * WSTR) = make_float4(a0.w, a1.w, a2.w, a3.w);

        float4 b0 = *(const float4*)(wb + EE + 0 * (2 * EE));
        float4 b1 = *(const float4*)(wb + EE + 1 * (2 * EE));
        float4 b2 = *(const float4*)(wb + EE + 2 * (2 * EE));
        float4 b3 = *(const float4*)(wb + EE + 3 * (2 * EE));
        float* d2 = s_w2 + (kg * 4) * WSTR + fg * 4;
        *(float4*)(d2 + 0 * WSTR) = make_float4(b0.x, b1.x, b2.x, b3.x);
        *(float4*)(d2 + 1 * WSTR) = make_float4(b0.y, b1.y, b2.y, b3.y);
        *(float4*)(d2 + 2 * WSTR) = make_float4(b0.z, b1.z, b2.z, b3.z);
        *(float4*)(d2 + 3 * WSTR) = make_float4(b0.w, b1.w, b2.w, b3.w);
    }

    __syncthreads();   // the only barrier

    // ---------------- sync-free mainloop over full K ------------------------
    unsigned long long acc1[2][2] = {};
    unsigned long long acc2[2][2] = {};

    const float* ax0 = s_x + (ty * 2 + 0) * XSTR;
    const float* ax1 = s_x + (ty * 2 + 1) * XSTR;

    #pragma unroll 1
    for (int ko = 0; ko < EE; ko += 16) {
        #pragma unroll
        for (int k2 = 0; k2 < 16; ++k2) {
            const int k = ko + k2;
            unsigned long long a0 = bcast2(ax0[k]);   // broadcast LDS.32
            unsigned long long a1 = bcast2(ax1[k]);
            const ulonglong2 w1 = *(const ulonglong2*)&s_w1[k * WSTR + tx * 4];
            const ulonglong2 w2 = *(const ulonglong2*)&s_w2[k * WSTR + tx * 4];

            fma2(acc1[0][0], a0, w1.x); fma2(acc1[0][1], a0, w1.y);
            fma2(acc1[1][0], a1, w1.x); fma2(acc1[1][1], a1, w1.y);

            fma2(acc2[0][0], a0, w2.x); fma2(acc2[0][1], a0, w2.y);
            fma2(acc2[1][0], a1, w2.x); fma2(acc2[1][1], a1, w2.y);
        }
    }

    // ---------------- epilogue ---------------------------------------------
    float4 bi = *(const float4*)&bias[f0 + tx * 4];

    #pragma unroll
    for (int i = 0; i < 2; ++i) {
        int m = m0 + ty * 2 + i;
        float2 p0 = *(float2*)&acc1[i][0];
        float2 p1 = *(float2*)&acc1[i][1];
        float2 q0 = *(float2*)&acc2[i][0];
        float2 q1 = *(float2*)&acc2[i][1];
        *(float4*)&g_pi [(size_t)m * EE + f0 + tx * 4] =
            make_float4(p0.x, p0.y, p1.x, p1.y);
        *(float4*)&g_pjb[(size_t)m * EE + f0 + tx * 4] =
            make_float4(q0.x + bi.x, q0.y + bi.y, q1.x + bi.z, q1.y + bi.w);
    }
}

// ---------------------------------------------------------------------------
// Kernel 2: broadcast add (frozen: 2048 blocks, ~43us — DRAM-write ceiling).
// ---------------------------------------------------------------------------
#define TI 4
#define TJ 32
#define E4 (EE / 4)

__global__ __launch_bounds__(256)
void add_kernel(float* __restrict__ out)
{
    __shared__ float4 s_pj[TJ * E4];   // 32 KB

    const int b   = blockIdx.z;
    const int i0  = blockIdx.y * TI;
    const int j0  = blockIdx.x * TJ;
    const int tid = threadIdx.x;
    const int e4  = tid & 63;
    const int jq  = tid >> 6;

    const float4* pi4 = (const float4*)g_pi  + (size_t)(b * SS + i0) * E4;
    const float4* pj4 = (const float4*)g_pjb + (size_t)(b * SS + j0) * E4;

    #pragma unroll
    for (int r = 0; r < 8; ++r)
        s_pj[tid + r * 256] = pj4[tid + r * 256];

    float4 pi_r[TI];
    #pragma unroll
    for (int i = 0; i < TI; ++i)
        pi_r[i] = pi4[i * E4 + e4];

    __syncthreads();

    float4* out4 = (float4*)out + ((size_t)(b * SS + i0) * SS + j0) * E4;

    #pragma unroll
    for (int jj = 0; jj < TJ / 4; ++jj) {
        int j = jq + jj * 4;
        float4 c = s_pj[j * E4 + e4];
        #pragma unroll
        for (int i = 0; i < TI; ++i) {
            float4 v = make_float4(pi_r[i].x + c.x, pi_r[i].y + c.y,
                                   pi_r[i].z + c.z, pi_r[i].w + c.w);
            __stcs(&out4[((size_t)i * SS + j) * E4 + e4], v);
        }
    }
}

// ---------------------------------------------------------------------------
extern "C" void kernel_launch(void* const* d_in, const int* in_sizes, int n_in,
                              void* d_out, int out_size)
{
    const float* x    = (const float*)d_in[0];   // component_repr [4,256,256]
    const float* W    = (const float*)d_in[1];   // W [256,512]
    const float* bias = (const float*)d_in[2];   // b [256]
    float* out = (float*)d_out;                  // [4,256,256,256]

    // raise dynamic smem cap (idempotent attribute set, not an allocation)
    cudaFuncSetAttribute(gemm_kernel,
                         cudaFuncAttributeMaxDynamicSharedMemorySize,
                         SMEM_BYTES);

    dim3 gGemm(MM / BM, EE / BN);                // 32 x 4 = 128 blocks
    gemm_kernel<<<gGemm, 256, SMEM_BYTES>>>(x, W, bias);

    dim3 gAdd(SS / TJ, SS / TI, BB);             // 8 x 64 x 4 = 2048 blocks
    add_kernel<<<gAdd, 256>>>(out);
}

// round 13
// speedup vs baseline: 1.0378x; 1.0355x over previous
#include <cuda_runtime.h>

// Problem shape (fixed by the dataset)
#define BB 4
#define SS 256
#define EE 256
#define MM (BB * SS)

// Scratch: pi[m,f] and (pj[m,f] + b[f]) — 1 MB each
__device__ float g_pi [MM * EE];
__device__ float g_pjb[MM * EE];

// ---------------------------------------------------------------------------
// Kernel 1: dual GEMM. 128 blocks x 128 threads, BM=32, BN=64, K=256 resident.
//  - W in SMEM (k-major, XOR-swizzled columns: element W[k][c] stored at
//    column c ^ (k & 60) -> W-transpose STS conflicts 16-way -> 4-way).
//  - x in REGISTERS (xr[16][4]); mainloop broadcasts via shfl.sync width=16
//    (each 16-lane half-warp owns 4 m-rows) -> zero x smem wavefronts.
//  - packed fma.rn.f32x2 accumulators; sync-free mainloop (one barrier).
// ---------------------------------------------------------------------------
#define BM 32
#define BN 64

#define WSTR 68                          // W row stride (floats): 272B = 17*16
#define SW_FLOATS (EE * WSTR)            // 17408 floats per matrix
#define SMEM_BYTES (2 * SW_FLOATS * 4)   // 139,264 B

__device__ __forceinline__ void fma2(unsigned long long& acc,
                                     unsigned long long a,
                                     unsigned long long b)
{
    asm("fma.rn.f32x2 %0, %1, %2, %0;" : "+l"(acc) : "l"(a), "l"(b));
}

__device__ __forceinline__ unsigned long long bcast2(float a)
{
    unsigned long long r;
    asm("mov.b64 %0, {%1, %1};" : "=l"(r) : "r"(__float_as_int(a)));
    return r;
}

__global__ __launch_bounds__(128)
void gemm_kernel(const float* __restrict__ x,
                 const float* __restrict__ W,
                 const float* __restrict__ bias)
{
    extern __shared__ float sm[];
    float* s_w1 = sm;                    // [256 k][WSTR], swizzled cols
    float* s_w2 = sm + SW_FLOATS;

    const int m0  = blockIdx.x * BM;
    const int f0  = blockIdx.y * BN;
    const int tid = threadIdx.x;

    const int ty  = tid >> 4;    // 0..7: m-group (4 rows each); = shfl group
    const int tx  = tid & 15;    // 0..15: f-quad; also lane-within-group

    // ---------------- x -> registers (no smem) ------------------------------
    // xr[c][i] = x[m0 + ty*4 + i][c*16 + tx] ; half-warp reads 64B contiguous.
    float xr[16][4];
    #pragma unroll
    for (int c = 0; c < 16; ++c) {
        #pragma unroll
        for (int i = 0; i < 4; ++i)
            xr[c][i] = x[(size_t)(m0 + ty * 4 + i) * EE + c * 16 + tx];
    }

    // ---------------- W load: 4x4 register transpose -> [k][f], swizzled ----
    // element W[k][c] stored at float offset k*WSTR + (c ^ (k & 60)).
    // For a 4x4 tile at (kg, fg): all rows k=kg*4+r share (k&60) = 4*(kg&15).
    #pragma unroll
    for (int i = 0; i < 8; ++i) {
        int t4 = tid + i * 128;               // 0..1023
        int fg = t4 >> 6;                     // f-group 0..15
        int kg = t4 & 63;                     // k-group 0..63
        const float* wb = W + (size_t)(f0 + fg * 4) * (2 * EE) + kg * 4;
        const int csw = (fg * 4) ^ ((kg & 15) << 2);

        float4 a0 = *(const float4*)(wb + 0 * (2 * EE));
        float4 a1 = *(const float4*)(wb + 1 * (2 * EE));
        float4 a2 = *(const float4*)(wb + 2 * (2 * EE));
        float4 a3 = *(const float4*)(wb + 3 * (2 * EE));
        float* d1 = s_w1 + (kg * 4) * WSTR + csw;
        *(float4*)(d1 + 0 * WSTR) = make_float4(a0.x, a1.x, a2.x, a3.x);
        *(float4*)(d1 + 1 * WSTR) = make_float4(a0.y, a1.y, a2.y, a3.y);
        *(float4*)(d1 + 2 * WSTR) = make_float4(a0.z, a1.z, a2.z, a3.z);
        *(float4*)(d1 + 3 * WSTR) = make_float4(a0.w, a1.w, a2.w, a3.w);

        float4 b0 = *(const float4*)(wb + EE + 0 * (2 * EE));
        float4 b1 = *(const float4*)(wb + EE + 1 * (2 * EE));
        float4 b2 = *(const float4*)(wb + EE + 2 * (2 * EE));
        float4 b3 = *(const float4*)(wb + EE + 3 * (2 * EE));
        float* d2 = s_w2 + (kg * 4) * WSTR + csw;
        *(float4*)(d2 + 0 * WSTR) = make_float4(b0.x, b1.x, b2.x, b3.x);
        *(float4*)(d2 + 1 * WSTR) = make_float4(b0.y, b1.y, b2.y, b3.y);
        *(float4*)(d2 + 2 * WSTR) = make_float4(b0.z, b1.z, b2.z, b3.z);
        *(float4*)(d2 + 3 * WSTR) = make_float4(b0.w, b1.w, b2.w, b3.w);
    }

    __syncthreads();   // the only barrier

    // ---------------- sync-free mainloop over full K ------------------------
    unsigned long long acc1[4][2] = {};
    unsigned long long acc2[4][2] = {};

    const int tx4 = tx * 4;

    #pragma unroll
    for (int ch = 0; ch < 16; ++ch) {
        // compile-time part of the swizzle for this chunk: bits 4-5 of k
        const int chsw = (ch * 16) & 48;
        const int txc  = tx4 ^ chsw;
        const float* wch = s_w1 + (ch * 16) * WSTR;

        #pragma unroll 4
        for (int k2 = 0; k2 < 16; ++k2) {
            // runtime swizzle part: bits 2-3 of k (constant across unroll-4 group)
            const int colsw = txc ^ (k2 & 12);
            const float* wrow = wch + k2 * WSTR + colsw;
            const ulonglong2 w1 = *(const ulonglong2*)wrow;
            const ulonglong2 w2 = *(const ulonglong2*)(wrow + SW_FLOATS);

            float x0 = __shfl_sync(0xffffffffu, xr[ch][0], k2, 16);
            float x1 = __shfl_sync(0xffffffffu, xr[ch][1], k2, 16);
            float x2 = __shfl_sync(0xffffffffu, xr[ch][2], k2, 16);
            float x3 = __shfl_sync(0xffffffffu, xr[ch][3], k2, 16);
            unsigned long long a0 = bcast2(x0);
            unsigned long long a1 = bcast2(x1);
            unsigned long long a2 = bcast2(x2);
            unsigned long long a3 = bcast2(x3);

            fma2(acc1[0][0], a0, w1.x); fma2(acc1[0][1], a0, w1.y);
            fma2(acc1[1][0], a1, w1.x); fma2(acc1[1][1], a1, w1.y);
            fma2(acc1[2][0], a2, w1.x); fma2(acc1[2][1], a2, w1.y);
            fma2(acc1[3][0], a3, w1.x); fma2(acc1[3][1], a3, w1.y);

            fma2(acc2[0][0], a0, w2.x); fma2(acc2[0][1], a0, w2.y);
            fma2(acc2[1][0], a1, w2.x); fma2(acc2[1][1], a1, w2.y);
            fma2(acc2[2][0], a2, w2.x); fma2(acc2[2][1], a2, w2.y);
            fma2(acc2[3][0], a3, w2.x); fma2(acc2[3][1], a3, w2.y);
        }
    }

    // ---------------- epilogue ---------------------------------------------
    float4 bi = *(const float4*)&bias[f0 + tx4];

    #pragma unroll
    for (int i = 0; i < 4; ++i) {
        int m = m0 + ty * 4 + i;
        float2 p0 = *(float2*)&acc1[i][0];
        float2 p1 = *(float2*)&acc1[i][1];
        float2 q0 = *(float2*)&acc2[i][0];
        float2 q1 = *(float2*)&acc2[i][1];
        *(float4*)&g_pi [(size_t)m * EE + f0 + tx4] =
            make_float4(p0.x, p0.y, p1.x, p1.y);
        *(float4*)&g_pjb[(size_t)m * EE + f0 + tx4] =
            make_float4(q0.x + bi.x, q0.y + bi.y, q1.x + bi.z, q1.y + bi.w);
    }
}

// ---------------------------------------------------------------------------
// Kernel 2: broadcast add (frozen: 2048 blocks, ~42us — DRAM-write ceiling).
// ---------------------------------------------------------------------------
#define TI 4
#define TJ 32
#define E4 (EE / 4)

__global__ __launch_bounds__(256)
void add_kernel(float* __restrict__ out)
{
    __shared__ float4 s_pj[TJ * E4];   // 32 KB

    const int b   = blockIdx.z;
    const int i0  = blockIdx.y * TI;
    const int j0  = blockIdx.x * TJ;
    const int tid = threadIdx.x;
    const int e4  = tid & 63;
    const int jq  = tid >> 6;

    const float4* pi4 = (const float4*)g_pi  + (size_t)(b * SS + i0) * E4;
    const float4* pj4 = (const float4*)g_pjb + (size_t)(b * SS + j0) * E4;

    #pragma unroll
    for (int r = 0; r < 8; ++r)
        s_pj[tid + r * 256] = pj4[tid + r * 256];

    float4 pi_r[TI];
    #pragma unroll
    for (int i = 0; i < TI; ++i)
        pi_r[i] = pi4[i * E4 + e4];

    __syncthreads();

    float4* out4 = (float4*)out + ((size_t)(b * SS + i0) * SS + j0) * E4;

    #pragma unroll
    for (int jj = 0; jj < TJ / 4; ++jj) {
        int j = jq + jj * 4;
        float4 c = s_pj[j * E4 + e4];
        #pragma unroll
        for (int i = 0; i < TI; ++i) {
            float4 v = make_float4(pi_r[i].x + c.x, pi_r[i].y + c.y,
                                   pi_r[i].z + c.z, pi_r[i].w + c.w);
            __stcs(&out4[((size_t)i * SS + j) * E4 + e4], v);
        }
    }
}

// ---------------------------------------------------------------------------
extern "C" void kernel_launch(void* const* d_in, const int* in_sizes, int n_in,
                              void* d_out, int out_size)
{
    const float* x    = (const float*)d_in[0];   // component_repr [4,256,256]
    const float* W    = (const float*)d_in[1];   // W [256,512]
    const float* bias = (const float*)d_in[2];   // b [256]
    float* out = (float*)d_out;                  // [4,256,256,256]

    // raise dynamic smem cap (idempotent attribute set, not an allocation)
    cudaFuncSetAttribute(gemm_kernel,
                         cudaFuncAttributeMaxDynamicSharedMemorySize,
                         SMEM_BYTES);

    dim3 gGemm(MM / BM, EE / BN);                // 32 x 4 = 128 blocks
    gemm_kernel<<<gGemm, 128, SMEM_BYTES>>>(x, W, bias);

    dim3 gAdd(SS / TJ, SS / TI, BB);             // 8 x 64 x 4 = 2048 blocks
    add_kernel<<<gAdd, 256>>>(out);
}